// round 15
// baseline (speedup 1.0000x reference)
#include <cuda_runtime.h>
#include <cuda_bf16.h>
#include <cstdint>

#define B_ 4
#define N_ 1024
#define D_ 768
#define H_ 12
#define ND3_ 2304
typedef unsigned long long u64t;

__device__ __nv_bfloat16 g_qs[B_ * H_ * N_ * 128];  // [bh][n][hi64|lo64]
__device__ __nv_bfloat16 g_ks[B_ * H_ * N_ * 128];
__device__ __nv_bfloat16 g_vs[B_ * H_ * N_ * 128];
__device__ unsigned short g_bidx[(size_t)B_ * N_ * N_];
__device__ __nv_bfloat16 g_a2[4096 * 1536];   // [m][hi(768)|lo(768)]
__device__ __nv_bfloat16 g_b2[2304 * 1536];   // W_qkv^T split
__device__ __nv_bfloat16 g_b2p[768 * 1536];   // W_proj^T split

__device__ __forceinline__ uint32_t smem_u32(const void* p) {
    uint32_t a;
    asm("{ .reg .u64 t; cvta.to.shared.u64 t, %1; cvt.u32.u64 %0, t; }"
        : "=r"(a) : "l"(p));
    return a;
}
__device__ __forceinline__ void mma16816(float* c, const uint32_t* a,
                                         const uint32_t* b) {
    asm volatile(
        "mma.sync.aligned.m16n8k16.row.col.f32.bf16.bf16.f32 "
        "{%0,%1,%2,%3}, {%4,%5,%6,%7}, {%8,%9}, {%0,%1,%2,%3};"
        : "+f"(c[0]), "+f"(c[1]), "+f"(c[2]), "+f"(c[3])
        : "r"(a[0]), "r"(a[1]), "r"(a[2]), "r"(a[3]), "r"(b[0]), "r"(b[1]));
}
__device__ __forceinline__ void ldsm4(uint32_t* r, uint32_t addr) {
    asm volatile("ldmatrix.sync.aligned.m8n8.x4.shared.b16 {%0,%1,%2,%3}, [%4];"
                 : "=r"(r[0]), "=r"(r[1]), "=r"(r[2]), "=r"(r[3]) : "r"(addr));
}
__device__ __forceinline__ void ldsm4t(uint32_t* r, uint32_t addr) {
    asm volatile(
        "ldmatrix.sync.aligned.m8n8.x4.trans.shared.b16 {%0,%1,%2,%3}, [%4];"
        : "=r"(r[0]), "=r"(r[1]), "=r"(r[2]), "=r"(r[3]) : "r"(addr));
}
__device__ __forceinline__ void cp16(uint32_t dst, const void* src) {
    asm volatile("cp.async.cg.shared.global [%0], [%1], 16;" :: "r"(dst), "l"(src));
}

// -- mma.sync bf16-split GEMM: (MT*32)x128 tile, KC=64, 3-stage, 256 thr ----
template <bool IS_QKV, int MT>
__global__ __launch_bounds__(256, 2) void mma_gemm(const float* __restrict__ bias,
                                                   float* __restrict__ out) {
    constexpr int ATILE = MT * 32 * 144;
    constexpr int STAGE = ATILE + 128 * 144;
    extern __shared__ char smem[];
    const int tid = threadIdx.x, wid = tid >> 5, lid = tid & 31;
    const int m0 = blockIdx.y * (MT * 32), n0 = blockIdx.x * 128;
    const int mw = wid >> 2, nw = wid & 3;
    const uint32_t sbase = smem_u32(smem);

    const __nv_bfloat16* a2 = g_a2 + (size_t)m0 * 1536;
    const __nv_bfloat16* b2 = (IS_QKV ? g_b2 : g_b2p) + (size_t)n0 * 1536;

    float acc[MT][4][4];
#pragma unroll
    for (int i = 0; i < MT; i++)
#pragma unroll
        for (int j = 0; j < 4; j++)
#pragma unroll
            for (int k = 0; k < 4; k++) acc[i][j][k] = 0.0f;

    auto load_chunk = [&](int c, int s) {
        int p = c / 12, cc = c % 12;
        int aoff = (p == 2 ? 768 : 0) + cc * 64;
        int boff = (p == 1 ? 768 : 0) + cc * 64;
        uint32_t da = sbase + s * STAGE;
        uint32_t db = da + ATILE;
#pragma unroll
        for (int i = 0; i < MT; i++) {
            int id = tid + i * 256;
            int row = id >> 3, seg = id & 7;
            cp16(da + row * 144 + seg * 16, a2 + (size_t)row * 1536 + aoff + seg * 8);
        }
#pragma unroll
        for (int i = 0; i < 4; i++) {
            int id = tid + i * 256;
            int row = id >> 3, seg = id & 7;
            cp16(db + row * 144 + seg * 16, b2 + (size_t)row * 1536 + boff + seg * 8);
        }
        asm volatile("cp.async.commit_group;" ::: "memory");
    };

    load_chunk(0, 0);
    load_chunk(1, 1);

    const int q = lid >> 3, r = lid & 7;
    const int aRow = mw * (MT * 16) + (q & 1) * 8 + r;
    const int aCol = (q >> 1) * 16;
    const int bRowE = nw * 32 + (q >> 1) * 8 + r;
    const int bCol = (q & 1) * 16;

    for (int c = 0; c < 36; c++) {
        int s = c % 3;
        asm volatile("cp.async.wait_group 1;" ::: "memory");
        __syncthreads();
        if (c + 2 < 36) load_chunk(c + 2, (c + 2) % 3);
        uint32_t sAb = sbase + s * STAGE;
        uint32_t sBb = sAb + ATILE;
#pragma unroll
        for (int ks = 0; ks < 4; ks++) {
            int koff = ks * 32;
            uint32_t bfr[4][2];
#pragma unroll
            for (int p = 0; p < 2; p++) {
                uint32_t t[4];
                ldsm4(t, sBb + (bRowE + p * 16) * 144 + koff + bCol);
                bfr[p * 2 + 0][0] = t[0];
                bfr[p * 2 + 0][1] = t[1];
                bfr[p * 2 + 1][0] = t[2];
                bfr[p * 2 + 1][1] = t[3];
            }
#pragma unroll
            for (int mt = 0; mt < MT; mt++) {
                uint32_t afr[4];
                ldsm4(afr, sAb + (aRow + mt * 16) * 144 + koff + aCol);
#pragma unroll
                for (int nt = 0; nt < 4; nt++) mma16816(acc[mt][nt], afr, bfr[nt]);
            }
        }
    }

#pragma unroll
    for (int mt = 0; mt < MT; mt++) {
#pragma unroll
        for (int half = 0; half < 2; half++) {
            int m = m0 + mw * (MT * 16) + mt * 16 + (lid >> 2) + half * 8;
            int mb = m >> 10, mr = m & 1023;
#pragma unroll
            for (int nt = 0; nt < 4; nt++) {
                int ng = n0 + nw * 32 + nt * 8 + 2 * (lid & 3);
                float2 v =
                    make_float2(acc[mt][nt][half * 2], acc[mt][nt][half * 2 + 1]);
                if (IS_QKV) {
                    int which = ng / D_, nm = ng % D_, hh = nm >> 6, c0 = nm & 63;
                    __nv_bfloat16* dst =
                        ((which == 0) ? g_qs : (which == 1) ? g_ks : g_vs) +
                        ((size_t)(mb * H_ + hh) * N_ + mr) * 128 + c0;
                    __nv_bfloat162 hv, lv;
                    hv.x = __float2bfloat16(v.x);
                    hv.y = __float2bfloat16(v.y);
                    lv.x = __float2bfloat16(v.x - __bfloat162float(hv.x));
                    lv.y = __float2bfloat16(v.y - __bfloat162float(hv.y));
                    *(uint32_t*)dst = *(uint32_t*)&hv;
                    *(uint32_t*)(dst + 64) = *(uint32_t*)&lv;
                } else {
                    v.x += bias[ng];
                    v.y += bias[ng + 1];
                    *(float2*)&out[(size_t)m * D_ + ng] = v;
                }
            }
        }
    }
}

// ---- prepA: X split (0..3071) + Wq split (3072..4799) ----
__global__ __launch_bounds__(256) void prepA(const float* __restrict__ X,
                                             const float* __restrict__ Wq) {
    const int tid = threadIdx.x;
    int bx = blockIdx.x;
    if (bx < 3072) {
        int idx = bx * 256 + tid;
        float4 v = ((const float4*)X)[idx];
        int m = idx / 192, kq = (idx % 192) * 4;
        __nv_bfloat16 h0 = __float2bfloat16(v.x), h1 = __float2bfloat16(v.y);
        __nv_bfloat16 h2 = __float2bfloat16(v.z), h3 = __float2bfloat16(v.w);
        __nv_bfloat16 l0 = __float2bfloat16(v.x - __bfloat162float(h0));
        __nv_bfloat16 l1 = __float2bfloat16(v.y - __bfloat162float(h1));
        __nv_bfloat16 l2 = __float2bfloat16(v.z - __bfloat162float(h2));
        __nv_bfloat16 l3 = __float2bfloat16(v.w - __bfloat162float(h3));
        __nv_bfloat16* rr = g_a2 + (size_t)m * 1536 + kq;
        rr[0] = h0; rr[1] = h1; rr[2] = h2; rr[3] = h3;
        rr[768] = l0; rr[769] = l1; rr[770] = l2; rr[771] = l3;
        return;
    }
    __shared__ float t[32][33];
    bx -= 3072;
    int kt = bx / 72, ntl = bx % 72;
    int k0 = kt * 32, n0 = ntl * 32;
    int tx = tid & 31, ty = tid >> 5;
#pragma unroll
    for (int i = 0; i < 4; i++)
        t[ty * 4 + i][tx] = Wq[(size_t)(k0 + ty * 4 + i) * ND3_ + n0 + tx];
    __syncthreads();
#pragma unroll
    for (int i = 0; i < 4; i++) {
        int n = n0 + ty * 4 + i;
        float x = t[tx][ty * 4 + i];
        __nv_bfloat16 h = __float2bfloat16(x);
        __nv_bfloat16 l = __float2bfloat16(x - __bfloat162float(h));
        g_b2[(size_t)n * 1536 + k0 + tx] = h;
        g_b2[(size_t)n * 1536 + 768 + k0 + tx] = l;
    }
}

// ---- prepB: bidx (0..255) + Wp split (256..831) ----
__device__ __forceinline__ int bucket_fn(int d) {
    int ret = (d > 0) ? 16 : 0;
    int n = (d < 0) ? -d : d;
    int v;
    if (n < 8) v = n;
    else { v = 33 - __clz(n * n); v = (v > 15) ? 15 : v; }
    return ret + v;
}

__global__ __launch_bounds__(256) void prepB(const float* __restrict__ coords,
                                             const float* __restrict__ Wp) {
    const int tid = threadIdx.x;
    int bx = blockIdx.x;
    if (bx < 256) {
        __shared__ short cjx[1024], cjy[1024];
        const int b = bx >> 6, i0 = (bx & 63) * 16;
        for (int t = tid; t < 1024; t += 256) {
            float2 c = *(const float2*)(coords + ((size_t)b * 1024 + t) * 2);
            cjx[t] = (short)(int)(c.x * 128.0f);
            cjy[t] = (short)(int)(c.y * 128.0f);
        }
        __syncthreads();
        unsigned short* outb = g_bidx + (size_t)b * N_ * N_ + (size_t)i0 * N_;
#pragma unroll
        for (int qq = 0; qq < 16; ++qq) {
            int item = tid + qq * 256;
            int i = item >> 8, j = (item & 255) * 4;
            int cx = cjx[i0 + i], cy = cjy[i0 + i];
            ushort4 r;
            r.x = (unsigned short)((bucket_fn(cx - cjx[j]) << 5) | bucket_fn(cy - cjy[j]));
            r.y = (unsigned short)((bucket_fn(cx - cjx[j + 1]) << 5) | bucket_fn(cy - cjy[j + 1]));
            r.z = (unsigned short)((bucket_fn(cx - cjx[j + 2]) << 5) | bucket_fn(cy - cjy[j + 2]));
            r.w = (unsigned short)((bucket_fn(cx - cjx[j + 3]) << 5) | bucket_fn(cy - cjy[j + 3]));
            *(ushort4*)(outb + (size_t)i * N_ + j) = r;
        }
        return;
    }
    __shared__ float t[32][33];
    bx -= 256;
    int kt = bx / 24, ntl = bx % 24;
    int k0 = kt * 32, n0 = ntl * 32;
    int tx = tid & 31, ty = tid >> 5;
#pragma unroll
    for (int i = 0; i < 4; i++)
        t[ty * 4 + i][tx] = Wp[(size_t)(k0 + ty * 4 + i) * D_ + n0 + tx];
    __syncthreads();
#pragma unroll
    for (int i = 0; i < 4; i++) {
        int n = n0 + ty * 4 + i;
        float x = t[tx][ty * 4 + i];
        __nv_bfloat16 h = __float2bfloat16(x);
        __nv_bfloat16 l = __float2bfloat16(x - __bfloat162float(h));
        g_b2p[(size_t)n * 1536 + k0 + tx] = h;
        g_b2p[(size_t)n * 1536 + 768 + k0 + tx] = l;
    }
}

// ------ tensor-core attention: j64, double-buffered K/V, cc-major QK ------
#define SQ_O 0                           // Q [128][136 bf16] stride 272B
#define STG_O(s) (34816 + (s) * 34816)   // stage: K [64][136] + V [64][136]
#define SV_REL 17408
#define ST_O 104448                      // tbl f32[1024]
#define SE_O(s) (108544 + (s) * 256)     // ejs f32[64] x2
#define ATTN_SMEM 109056

__global__ __launch_bounds__(256, 2) void attn3_kernel(
    const float* __restrict__ elev, const float* __restrict__ bias_table,
    const float* __restrict__ alphap) {
    extern __shared__ char smc[];
    const uint32_t sb = smem_u32(smc);
    float* tbl = (float*)(smc + ST_O);
    const int tid = threadIdx.x, w = tid >> 5, l = tid & 31;
    const int i0 = blockIdx.x * 128, h = blockIdx.y, b = blockIdx.z;

    const __nv_bfloat16* qsrc = g_qs + ((size_t)(b * H_ + h) * N_ + i0) * 128;
    const __nv_bfloat16* ksrc = g_ks + ((size_t)(b * H_ + h) * N_) * 128;
    const __nv_bfloat16* vsrc = g_vs + ((size_t)(b * H_ + h) * N_) * 128;

#pragma unroll
    for (int it = 0; it < 8; it++) {
        int seg = tid + it * 256;
        int row = seg >> 4, s16 = seg & 15;
        cp16(sb + SQ_O + row * 272 + s16 * 16, qsrc + row * 128 + s16 * 8);
    }
#pragma unroll
    for (int it = 0; it < 4; it++) {
        int seg = tid + it * 256;
        int row = seg >> 4, s16 = seg & 15;
        cp16(sb + STG_O(0) + row * 272 + s16 * 16, ksrc + (size_t)row * 128 + s16 * 8);
        cp16(sb + STG_O(0) + SV_REL + row * 272 + s16 * 16,
             vsrc + (size_t)row * 128 + s16 * 8);
    }
    if (tid < 16) cp16(sb + SE_O(0) + tid * 16, elev + b * N_ + tid * 4);
    asm volatile("cp.async.commit_group;" ::: "memory");

    for (int t = tid; t < 1024; t += 256) tbl[t] = bias_table[t * H_ + h];

    const int lq = l >> 2, lr = l & 3;
    const int r0g = i0 + w * 16 + lq;
    const float eir0 = elev[b * N_ + r0g] * 1e-3f;
    const float eir1 = elev[b * N_ + r0g + 8] * 1e-3f;
    const float alpha = *alphap;

    float O[8][4];
#pragma unroll
    for (int i = 0; i < 8; i++)
#pragma unroll
        for (int j = 0; j < 4; j++) O[i][j] = 0.0f;
    float lrow0 = 0.0f, lrow1 = 0.0f;

    const unsigned short* bsrc0 =
        g_bidx + ((size_t)b * N_ + (size_t)(w * 16 + lq) + i0) * N_;
    const unsigned short* bsrc1 = bsrc0 + (size_t)8 * N_;

    asm volatile("cp.async.wait_group 0;" ::: "memory");
    __syncthreads();

    const uint32_t qrow = sb + SQ_O + (w * 16 + (l & 15)) * 272 + (l >> 4) * 16;
    const int krow_off = ((l >> 4) << 3) + (l & 7);
    const int ksel = ((l >> 3) & 1) * 16;

    for (int jt = 0; jt < 16; jt++) {
        const int j0 = jt * 64;
        const int s = jt & 1;
        if (jt < 15) {
#pragma unroll
            for (int it = 0; it < 4; it++) {
                int seg = tid + it * 256;
                int row = seg >> 4, s16 = seg & 15;
                cp16(sb + STG_O(s ^ 1) + row * 272 + s16 * 16,
                     ksrc + (size_t)(j0 + 64 + row) * 128 + s16 * 8);
                cp16(sb + STG_O(s ^ 1) + SV_REL + row * 272 + s16 * 16,
                     vsrc + (size_t)(j0 + 64 + row) * 128 + s16 * 8);
            }
            if (tid < 16)
                cp16(sb + SE_O(s ^ 1) + tid * 16, elev + b * N_ + j0 + 64 + tid * 4);
            asm volatile("cp.async.commit_group;" ::: "memory");
        }
        const uint32_t kbase = sb + STG_O(s);
        const uint32_t vbase = kbase + SV_REL;
        const float* ejs = (float*)(smc + SE_O(s));

        // S = Q K^T, cc-major: load Q_hi/Q_lo + K_hi/K_lo once per chunk
        float S[8][4];
#pragma unroll
        for (int i = 0; i < 8; i++)
#pragma unroll
            for (int j = 0; j < 4; j++) S[i][j] = 0.0f;
#pragma unroll
        for (int cc = 0; cc < 4; cc++) {
            const int hi_off = cc * 32, lo_off = 128 + cc * 32;
            uint32_t a_hi[4], a_lo[4];
            ldsm4(a_hi, qrow + hi_off);
            ldsm4(a_lo, qrow + lo_off);
#pragma unroll
            for (int jp = 0; jp < 4; jp++) {
                uint32_t krow = kbase + (jp * 16 + krow_off) * 272 + ksel;
                uint32_t th[4], tl[4];
                ldsm4(th, krow + hi_off);
                ldsm4(tl, krow + lo_off);
                mma16816(S[2 * jp], a_hi, th);
                mma16816(S[2 * jp + 1], a_hi, th + 2);
                mma16816(S[2 * jp], a_hi, tl);
                mma16816(S[2 * jp + 1], a_hi, tl + 2);
                mma16816(S[2 * jp], a_lo, th);
                mma16816(S[2 * jp + 1], a_lo, th + 2);
            }
        }

        // softmax (fixed-max) + pack P hi/lo fragments; bidx direct LDG
        uint32_t ph[16], pl[16];
#pragma unroll
        for (int t = 0; t < 8; t++) {
            int cl = 8 * t + 2 * lr;
            uint32_t ba = *(const uint32_t*)(bsrc0 + j0 + cl);
            uint32_t bb = *(const uint32_t*)(bsrc1 + j0 + cl);
            float ej0 = ejs[cl], ej1 = ejs[cl + 1];
            float e00 = fminf(fmaxf(-alpha * fmaxf(ej0 * 1e-3f - eir0, 0.f), -10.f), 0.f);
            float e01 = fminf(fmaxf(-alpha * fmaxf(ej1 * 1e-3f - eir0, 0.f), -10.f), 0.f);
            float e10 = fminf(fmaxf(-alpha * fmaxf(ej0 * 1e-3f - eir1, 0.f), -10.f), 0.f);
            float e11 = fminf(fmaxf(-alpha * fmaxf(ej1 * 1e-3f - eir1, 0.f), -10.f), 0.f);
            float p0 = __expf(S[t][0] * 0.125f + tbl[ba & 0xffff] + e00);
            float p1 = __expf(S[t][1] * 0.125f + tbl[ba >> 16] + e01);
            float p2 = __expf(S[t][2] * 0.125f + tbl[bb & 0xffff] + e10);
            float p3 = __expf(S[t][3] * 0.125f + tbl[bb >> 16] + e11);
            lrow0 += p0 + p1;
            lrow1 += p2 + p3;
            __nv_bfloat162 hA, hB, lA, lB;
            hA.x = __float2bfloat16(p0); hA.y = __float2bfloat16(p1);
            hB.x = __float2bfloat16(p2); hB.y = __float2bfloat16(p3);
            lA.x = __float2bfloat16(p0 - __bfloat162float(hA.x));
            lA.y = __float2bfloat16(p1 - __bfloat162float(hA.y));
            lB.x = __float2bfloat16(p2 - __bfloat162float(hB.x));
            lB.y = __float2bfloat16(p3 - __bfloat162float(hB.y));
            ph[t * 2] = *(uint32_t*)&hA; ph[t * 2 + 1] = *(uint32_t*)&hB;
            pl[t * 2] = *(uint32_t*)&lA; pl[t * 2 + 1] = *(uint32_t*)&lB;
        }

        // O += P V  (hh + lh + hl)
#pragma unroll
        for (int c = 0; c < 4; c++) {
            const uint32_t* ah = ph + 4 * c;
            const uint32_t* al = pl + 4 * c;
            uint32_t vrow = vbase +
                            (c * 16 + (((l >> 3) & 1) << 3) + (l & 7)) * 272 +
                            (l >> 4) * 16;
#pragma unroll
            for (int dp = 0; dp < 4; dp++) {
                uint32_t tv[4];
                ldsm4t(tv, vrow + dp * 32);
                mma16816(O[2 * dp], ah, tv);
                mma16816(O[2 * dp + 1], ah, tv + 2);
                mma16816(O[2 * dp], al, tv);
                mma16816(O[2 * dp + 1], al, tv + 2);
                uint32_t tw[4];
                ldsm4t(tw, vrow + 128 + dp * 32);
                mma16816(O[2 * dp], ah, tw);
                mma16816(O[2 * dp + 1], ah, tw + 2);
            }
        }

        if (jt < 15) asm volatile("cp.async.wait_group 0;" ::: "memory");
        __syncthreads();
    }

    // finalize
    lrow0 += __shfl_xor_sync(0xffffffff, lrow0, 1);
    lrow0 += __shfl_xor_sync(0xffffffff, lrow0, 2);
    lrow1 += __shfl_xor_sync(0xffffffff, lrow1, 1);
    lrow1 += __shfl_xor_sync(0xffffffff, lrow1, 2);
    float inv0 = 1.0f / lrow0, inv1 = 1.0f / lrow1;
#pragma unroll
    for (int dt = 0; dt < 8; dt++) {
        int col = h * 64 + dt * 8 + 2 * lr;
        float o0 = O[dt][0] * inv0, o1 = O[dt][1] * inv0;
        float o2 = O[dt][2] * inv1, o3 = O[dt][3] * inv1;
        __nv_bfloat16* d0 = g_a2 + (size_t)(b * N_ + r0g) * 1536 + col;
        __nv_bfloat16* d1 = g_a2 + (size_t)(b * N_ + r0g + 8) * 1536 + col;
        __nv_bfloat162 hv, lv;
        hv.x = __float2bfloat16(o0); hv.y = __float2bfloat16(o1);
        lv.x = __float2bfloat16(o0 - __bfloat162float(hv.x));
        lv.y = __float2bfloat16(o1 - __bfloat162float(hv.y));
        *(uint32_t*)d0 = *(uint32_t*)&hv;
        *(uint32_t*)(d0 + 768) = *(uint32_t*)&lv;
        hv.x = __float2bfloat16(o2); hv.y = __float2bfloat16(o3);
        lv.x = __float2bfloat16(o2 - __bfloat162float(hv.x));
        lv.y = __float2bfloat16(o3 - __bfloat162float(hv.y));
        *(uint32_t*)d1 = *(uint32_t*)&hv;
        *(uint32_t*)(d1 + 768) = *(uint32_t*)&lv;
    }
}

extern "C" void kernel_launch(void* const* d_in, const int* in_sizes, int n_in,
                              void* d_out, int out_size) {
    const float* x = (const float*)d_in[0];
    const float* coords = (const float*)d_in[1];
    const float* elev = (const float*)d_in[2];
    const float* W_qkv = (const float*)d_in[3];
    const float* W_proj = (const float*)d_in[4];
    const float* b_proj = (const float*)d_in[5];
    const float* bias_table = (const float*)d_in[6];
    const float* alpha = (const float*)d_in[7];
    float* out = (float*)d_out;

    static cudaStream_t s1 = nullptr;
    static cudaEvent_t evFork = nullptr, evJoin = nullptr;
    if (!s1) {
        cudaStreamCreateWithFlags(&s1, cudaStreamNonBlocking);
        cudaEventCreateWithFlags(&evFork, cudaEventDisableTiming);
        cudaEventCreateWithFlags(&evJoin, cudaEventDisableTiming);
    }

    cudaFuncSetAttribute(attn3_kernel, cudaFuncAttributeMaxDynamicSharedMemorySize,
                         ATTN_SMEM);
    cudaFuncSetAttribute((const void*)mma_gemm<true, 2>,
                         cudaFuncAttributeMaxDynamicSharedMemorySize,
                         3 * (2 * 32 * 144 + 128 * 144));
    cudaFuncSetAttribute((const void*)mma_gemm<false, 2>,
                         cudaFuncAttributeMaxDynamicSharedMemorySize,
                         3 * (2 * 32 * 144 + 128 * 144));

    // fork: prepB (bidx + Wp) runs concurrently with prepA + qkv
    cudaEventRecord(evFork, 0);
    cudaStreamWaitEvent(s1, evFork, 0);
    prepB<<<832, 256, 0, s1>>>(coords, W_proj);
    cudaEventRecord(evJoin, s1);

    prepA<<<4800, 256>>>(x, W_qkv);
    mma_gemm<true, 2><<<dim3(ND3_ / 128, 64), 256,
                        3 * (2 * 32 * 144 + 128 * 144)>>>(nullptr, nullptr);
    cudaStreamWaitEvent(0, evJoin, 0);
    attn3_kernel<<<dim3(N_ / 128, H_, B_), 256, ATTN_SMEM>>>(elev, bias_table, alpha);
    mma_gemm<false, 2><<<dim3(D_ / 128, 64), 256,
                         3 * (2 * 32 * 144 + 128 * 144)>>>(b_proj, out);
}

// round 16
// speedup vs baseline: 1.0614x; 1.0614x over previous
#include <cuda_runtime.h>
#include <cuda_bf16.h>
#include <cstdint>

#define B_ 4
#define N_ 1024
#define D_ 768
#define H_ 12
#define ND3_ 2304
typedef unsigned long long u64t;

__device__ __nv_bfloat16 g_qs[B_ * H_ * N_ * 128];  // [bh][n][hi64|lo64]
__device__ __nv_bfloat16 g_ks[B_ * H_ * N_ * 128];
__device__ __nv_bfloat16 g_vs[B_ * H_ * N_ * 128];
__device__ unsigned short g_bidx[(size_t)B_ * N_ * N_];
__device__ __nv_bfloat16 g_a2[4096 * 1536];   // [m][hi(768)|lo(768)]
__device__ __nv_bfloat16 g_b2[2304 * 1536];   // W_qkv^T split
__device__ __nv_bfloat16 g_b2p[768 * 1536];   // W_proj^T split

__device__ __forceinline__ uint32_t smem_u32(const void* p) {
    uint32_t a;
    asm("{ .reg .u64 t; cvta.to.shared.u64 t, %1; cvt.u32.u64 %0, t; }"
        : "=r"(a) : "l"(p));
    return a;
}
__device__ __forceinline__ void mma16816(float* c, const uint32_t* a,
                                         const uint32_t* b) {
    asm volatile(
        "mma.sync.aligned.m16n8k16.row.col.f32.bf16.bf16.f32 "
        "{%0,%1,%2,%3}, {%4,%5,%6,%7}, {%8,%9}, {%0,%1,%2,%3};"
        : "+f"(c[0]), "+f"(c[1]), "+f"(c[2]), "+f"(c[3])
        : "r"(a[0]), "r"(a[1]), "r"(a[2]), "r"(a[3]), "r"(b[0]), "r"(b[1]));
}
__device__ __forceinline__ void ldsm4(uint32_t* r, uint32_t addr) {
    asm volatile("ldmatrix.sync.aligned.m8n8.x4.shared.b16 {%0,%1,%2,%3}, [%4];"
                 : "=r"(r[0]), "=r"(r[1]), "=r"(r[2]), "=r"(r[3]) : "r"(addr));
}
__device__ __forceinline__ void ldsm4t(uint32_t* r, uint32_t addr) {
    asm volatile(
        "ldmatrix.sync.aligned.m8n8.x4.trans.shared.b16 {%0,%1,%2,%3}, [%4];"
        : "=r"(r[0]), "=r"(r[1]), "=r"(r[2]), "=r"(r[3]) : "r"(addr));
}
__device__ __forceinline__ void cp16(uint32_t dst, const void* src) {
    asm volatile("cp.async.cg.shared.global [%0], [%1], 16;" :: "r"(dst), "l"(src));
}

// -- mma.sync bf16-split GEMM: (MT*32)x128 tile, KC=64, 3-stage, 256 thr ----
template <bool IS_QKV, int MT>
__global__ __launch_bounds__(256, 2) void mma_gemm(const float* __restrict__ bias,
                                                   float* __restrict__ out) {
    constexpr int ATILE = MT * 32 * 144;
    constexpr int STAGE = ATILE + 128 * 144;
    extern __shared__ char smem[];
    const int tid = threadIdx.x, wid = tid >> 5, lid = tid & 31;
    const int m0 = blockIdx.y * (MT * 32), n0 = blockIdx.x * 128;
    const int mw = wid >> 2, nw = wid & 3;
    const uint32_t sbase = smem_u32(smem);

    const __nv_bfloat16* a2 = g_a2 + (size_t)m0 * 1536;
    const __nv_bfloat16* b2 = (IS_QKV ? g_b2 : g_b2p) + (size_t)n0 * 1536;

    float acc[MT][4][4];
#pragma unroll
    for (int i = 0; i < MT; i++)
#pragma unroll
        for (int j = 0; j < 4; j++)
#pragma unroll
            for (int k = 0; k < 4; k++) acc[i][j][k] = 0.0f;

    auto load_chunk = [&](int c, int s) {
        int p = c / 12, cc = c % 12;
        int aoff = (p == 2 ? 768 : 0) + cc * 64;
        int boff = (p == 1 ? 768 : 0) + cc * 64;
        uint32_t da = sbase + s * STAGE;
        uint32_t db = da + ATILE;
#pragma unroll
        for (int i = 0; i < MT; i++) {
            int id = tid + i * 256;
            int row = id >> 3, seg = id & 7;
            cp16(da + row * 144 + seg * 16, a2 + (size_t)row * 1536 + aoff + seg * 8);
        }
#pragma unroll
        for (int i = 0; i < 4; i++) {
            int id = tid + i * 256;
            int row = id >> 3, seg = id & 7;
            cp16(db + row * 144 + seg * 16, b2 + (size_t)row * 1536 + boff + seg * 8);
        }
        asm volatile("cp.async.commit_group;" ::: "memory");
    };

    load_chunk(0, 0);
    load_chunk(1, 1);

    const int q = lid >> 3, r = lid & 7;
    const int aRow = mw * (MT * 16) + (q & 1) * 8 + r;
    const int aCol = (q >> 1) * 16;
    const int bRowE = nw * 32 + (q >> 1) * 8 + r;
    const int bCol = (q & 1) * 16;

    for (int c = 0; c < 36; c++) {
        int s = c % 3;
        asm volatile("cp.async.wait_group 1;" ::: "memory");
        __syncthreads();
        if (c + 2 < 36) load_chunk(c + 2, (c + 2) % 3);
        uint32_t sAb = sbase + s * STAGE;
        uint32_t sBb = sAb + ATILE;
#pragma unroll
        for (int ks = 0; ks < 4; ks++) {
            int koff = ks * 32;
            uint32_t bfr[4][2];
#pragma unroll
            for (int p = 0; p < 2; p++) {
                uint32_t t[4];
                ldsm4(t, sBb + (bRowE + p * 16) * 144 + koff + bCol);
                bfr[p * 2 + 0][0] = t[0];
                bfr[p * 2 + 0][1] = t[1];
                bfr[p * 2 + 1][0] = t[2];
                bfr[p * 2 + 1][1] = t[3];
            }
#pragma unroll
            for (int mt = 0; mt < MT; mt++) {
                uint32_t afr[4];
                ldsm4(afr, sAb + (aRow + mt * 16) * 144 + koff + aCol);
#pragma unroll
                for (int nt = 0; nt < 4; nt++) mma16816(acc[mt][nt], afr, bfr[nt]);
            }
        }
    }

#pragma unroll
    for (int mt = 0; mt < MT; mt++) {
#pragma unroll
        for (int half = 0; half < 2; half++) {
            int m = m0 + mw * (MT * 16) + mt * 16 + (lid >> 2) + half * 8;
            int mb = m >> 10, mr = m & 1023;
#pragma unroll
            for (int nt = 0; nt < 4; nt++) {
                int ng = n0 + nw * 32 + nt * 8 + 2 * (lid & 3);
                float2 v =
                    make_float2(acc[mt][nt][half * 2], acc[mt][nt][half * 2 + 1]);
                if (IS_QKV) {
                    int which = ng / D_, nm = ng % D_, hh = nm >> 6, c0 = nm & 63;
                    __nv_bfloat16* dst =
                        ((which == 0) ? g_qs : (which == 1) ? g_ks : g_vs) +
                        ((size_t)(mb * H_ + hh) * N_ + mr) * 128 + c0;
                    __nv_bfloat162 hv, lv;
                    hv.x = __float2bfloat16(v.x);
                    hv.y = __float2bfloat16(v.y);
                    lv.x = __float2bfloat16(v.x - __bfloat162float(hv.x));
                    lv.y = __float2bfloat16(v.y - __bfloat162float(hv.y));
                    *(uint32_t*)dst = *(uint32_t*)&hv;
                    *(uint32_t*)(dst + 64) = *(uint32_t*)&lv;
                } else {
                    v.x += bias[ng];
                    v.y += bias[ng + 1];
                    *(float2*)&out[(size_t)m * D_ + ng] = v;
                }
            }
        }
    }
}

// ---- fused prep: split X (0..3071) | bidx (3072..3327) | W splits (3328+) ----
__device__ __forceinline__ int bucket_fn(int d) {
    int ret = (d > 0) ? 16 : 0;
    int n = (d < 0) ? -d : d;
    int v;
    if (n < 8) v = n;
    else { v = 33 - __clz(n * n); v = (v > 15) ? 15 : v; }
    return ret + v;
}

__global__ __launch_bounds__(256) void prep_all(const float* __restrict__ X,
                                                const float* __restrict__ coords,
                                                const float* __restrict__ Wq,
                                                const float* __restrict__ Wp) {
    const int tid = threadIdx.x;
    int bx = blockIdx.x;
    if (bx < 3072) {
        int idx = bx * 256 + tid;
        float4 v = ((const float4*)X)[idx];
        int m = idx / 192, kq = (idx % 192) * 4;
        __nv_bfloat16 h0 = __float2bfloat16(v.x), h1 = __float2bfloat16(v.y);
        __nv_bfloat16 h2 = __float2bfloat16(v.z), h3 = __float2bfloat16(v.w);
        __nv_bfloat16 l0 = __float2bfloat16(v.x - __bfloat162float(h0));
        __nv_bfloat16 l1 = __float2bfloat16(v.y - __bfloat162float(h1));
        __nv_bfloat16 l2 = __float2bfloat16(v.z - __bfloat162float(h2));
        __nv_bfloat16 l3 = __float2bfloat16(v.w - __bfloat162float(h3));
        __nv_bfloat16* rr = g_a2 + (size_t)m * 1536 + kq;
        rr[0] = h0; rr[1] = h1; rr[2] = h2; rr[3] = h3;
        rr[768] = l0; rr[769] = l1; rr[770] = l2; rr[771] = l3;
        return;
    }
    if (bx < 3328) {
        __shared__ short cjx[1024], cjy[1024];
        const int bid = bx - 3072;
        const int b = bid >> 6, i0 = (bid & 63) * 16;
        for (int t = tid; t < 1024; t += 256) {
            float2 c = *(const float2*)(coords + ((size_t)b * 1024 + t) * 2);
            cjx[t] = (short)(int)(c.x * 128.0f);
            cjy[t] = (short)(int)(c.y * 128.0f);
        }
        __syncthreads();
        unsigned short* outb = g_bidx + (size_t)b * N_ * N_ + (size_t)i0 * N_;
#pragma unroll
        for (int qq = 0; qq < 16; ++qq) {
            int item = tid + qq * 256;
            int i = item >> 8, j = (item & 255) * 4;
            int cx = cjx[i0 + i], cy = cjy[i0 + i];
            ushort4 r;
            r.x = (unsigned short)((bucket_fn(cx - cjx[j]) << 5) | bucket_fn(cy - cjy[j]));
            r.y = (unsigned short)((bucket_fn(cx - cjx[j + 1]) << 5) | bucket_fn(cy - cjy[j + 1]));
            r.z = (unsigned short)((bucket_fn(cx - cjx[j + 2]) << 5) | bucket_fn(cy - cjy[j + 2]));
            r.w = (unsigned short)((bucket_fn(cx - cjx[j + 3]) << 5) | bucket_fn(cy - cjy[j + 3]));
            *(ushort4*)(outb + (size_t)i * N_ + j) = r;
        }
        return;
    }
    __shared__ float t[32][33];
    bx -= 3328;
    const float* W;
    int ncols, kt, ntl;
    __nv_bfloat16* dst;
    if (bx < 1728) {
        W = Wq; ncols = ND3_; dst = g_b2;
        kt = bx / 72; ntl = bx % 72;
    } else {
        bx -= 1728;
        W = Wp; ncols = D_; dst = g_b2p;
        kt = bx / 24; ntl = bx % 24;
    }
    int k0 = kt * 32, n0 = ntl * 32;
    int tx = tid & 31, ty = tid >> 5;
#pragma unroll
    for (int i = 0; i < 4; i++)
        t[ty * 4 + i][tx] = W[(size_t)(k0 + ty * 4 + i) * ncols + n0 + tx];
    __syncthreads();
#pragma unroll
    for (int i = 0; i < 4; i++) {
        int n = n0 + ty * 4 + i;
        float x = t[tx][ty * 4 + i];
        __nv_bfloat16 h = __float2bfloat16(x);
        __nv_bfloat16 l = __float2bfloat16(x - __bfloat162float(h));
        dst[(size_t)n * 1536 + k0 + tx] = h;
        dst[(size_t)n * 1536 + 768 + k0 + tx] = l;
    }
}

// ------ tensor-core attention: j64, double-buffered K/V, cc-major QK ------
#define SQ_O 0                           // Q [128][136 bf16] stride 272B
#define STG_O(s) (34816 + (s) * 34816)   // stage: K [64][136] + V [64][136]
#define SV_REL 17408
#define ST_O 104448                      // tbl f32[1024]
#define SE_O(s) (108544 + (s) * 256)     // ejs f32[64] x2
#define ATTN_SMEM 109056

__global__ __launch_bounds__(256, 2) void attn3_kernel(
    const float* __restrict__ elev, const float* __restrict__ bias_table,
    const float* __restrict__ alphap) {
    extern __shared__ char smc[];
    const uint32_t sb = smem_u32(smc);
    float* tbl = (float*)(smc + ST_O);
    const int tid = threadIdx.x, w = tid >> 5, l = tid & 31;
    const int i0 = blockIdx.x * 128, h = blockIdx.y, b = blockIdx.z;

    const __nv_bfloat16* qsrc = g_qs + ((size_t)(b * H_ + h) * N_ + i0) * 128;
    const __nv_bfloat16* ksrc = g_ks + ((size_t)(b * H_ + h) * N_) * 128;
    const __nv_bfloat16* vsrc = g_vs + ((size_t)(b * H_ + h) * N_) * 128;

#pragma unroll
    for (int it = 0; it < 8; it++) {
        int seg = tid + it * 256;
        int row = seg >> 4, s16 = seg & 15;
        cp16(sb + SQ_O + row * 272 + s16 * 16, qsrc + row * 128 + s16 * 8);
    }
#pragma unroll
    for (int it = 0; it < 4; it++) {
        int seg = tid + it * 256;
        int row = seg >> 4, s16 = seg & 15;
        cp16(sb + STG_O(0) + row * 272 + s16 * 16, ksrc + (size_t)row * 128 + s16 * 8);
        cp16(sb + STG_O(0) + SV_REL + row * 272 + s16 * 16,
             vsrc + (size_t)row * 128 + s16 * 8);
    }
    if (tid < 16) cp16(sb + SE_O(0) + tid * 16, elev + b * N_ + tid * 4);
    asm volatile("cp.async.commit_group;" ::: "memory");

    for (int t = tid; t < 1024; t += 256) tbl[t] = bias_table[t * H_ + h];

    const int lq = l >> 2, lr = l & 3;
    const int r0g = i0 + w * 16 + lq;
    const float eir0 = elev[b * N_ + r0g] * 1e-3f;
    const float eir1 = elev[b * N_ + r0g + 8] * 1e-3f;
    const float alpha = *alphap;

    float O[8][4];
#pragma unroll
    for (int i = 0; i < 8; i++)
#pragma unroll
        for (int j = 0; j < 4; j++) O[i][j] = 0.0f;
    float lrow0 = 0.0f, lrow1 = 0.0f;

    const unsigned short* bsrc0 =
        g_bidx + ((size_t)b * N_ + (size_t)(w * 16 + lq) + i0) * N_;
    const unsigned short* bsrc1 = bsrc0 + (size_t)8 * N_;

    asm volatile("cp.async.wait_group 0;" ::: "memory");
    __syncthreads();

    const uint32_t qrow = sb + SQ_O + (w * 16 + (l & 15)) * 272 + (l >> 4) * 16;
    const int krow_off = ((l >> 4) << 3) + (l & 7);
    const int ksel = ((l >> 3) & 1) * 16;

    for (int jt = 0; jt < 16; jt++) {
        const int j0 = jt * 64;
        const int s = jt & 1;
        if (jt < 15) {
#pragma unroll
            for (int it = 0; it < 4; it++) {
                int seg = tid + it * 256;
                int row = seg >> 4, s16 = seg & 15;
                cp16(sb + STG_O(s ^ 1) + row * 272 + s16 * 16,
                     ksrc + (size_t)(j0 + 64 + row) * 128 + s16 * 8);
                cp16(sb + STG_O(s ^ 1) + SV_REL + row * 272 + s16 * 16,
                     vsrc + (size_t)(j0 + 64 + row) * 128 + s16 * 8);
            }
            if (tid < 16)
                cp16(sb + SE_O(s ^ 1) + tid * 16, elev + b * N_ + j0 + 64 + tid * 4);
            asm volatile("cp.async.commit_group;" ::: "memory");
        }
        const uint32_t kbase = sb + STG_O(s);
        const uint32_t vbase = kbase + SV_REL;
        const float* ejs = (float*)(smc + SE_O(s));

        // S = Q K^T, cc-major: load Q_hi/Q_lo + K_hi/K_lo once per chunk
        float S[8][4];
#pragma unroll
        for (int i = 0; i < 8; i++)
#pragma unroll
            for (int j = 0; j < 4; j++) S[i][j] = 0.0f;
#pragma unroll
        for (int cc = 0; cc < 4; cc++) {
            const int hi_off = cc * 32, lo_off = 128 + cc * 32;
            uint32_t a_hi[4], a_lo[4];
            ldsm4(a_hi, qrow + hi_off);
            ldsm4(a_lo, qrow + lo_off);
#pragma unroll
            for (int jp = 0; jp < 4; jp++) {
                uint32_t krow = kbase + (jp * 16 + krow_off) * 272 + ksel;
                uint32_t th[4], tl[4];
                ldsm4(th, krow + hi_off);
                ldsm4(tl, krow + lo_off);
                mma16816(S[2 * jp], a_hi, th);
                mma16816(S[2 * jp + 1], a_hi, th + 2);
                mma16816(S[2 * jp], a_hi, tl);
                mma16816(S[2 * jp + 1], a_hi, tl + 2);
                mma16816(S[2 * jp], a_lo, th);
                mma16816(S[2 * jp + 1], a_lo, th + 2);
            }
        }

        // softmax (fixed-max) + pack P hi/lo fragments; bidx direct LDG
        // elev bias: value is always <= 0 (alpha>0), so no upper clamp needed.
        uint32_t ph[16], pl[16];
#pragma unroll
        for (int t = 0; t < 8; t++) {
            int cl = 8 * t + 2 * lr;
            uint32_t ba = *(const uint32_t*)(bsrc0 + j0 + cl);
            uint32_t bb = *(const uint32_t*)(bsrc1 + j0 + cl);
            float ej0s = ejs[cl] * 1e-3f, ej1s = ejs[cl + 1] * 1e-3f;
            float e00 = fmaxf(-alpha * fmaxf(ej0s - eir0, 0.f), -10.f);
            float e01 = fmaxf(-alpha * fmaxf(ej1s - eir0, 0.f), -10.f);
            float e10 = fmaxf(-alpha * fmaxf(ej0s - eir1, 0.f), -10.f);
            float e11 = fmaxf(-alpha * fmaxf(ej1s - eir1, 0.f), -10.f);
            float p0 = __expf(S[t][0] * 0.125f + tbl[ba & 0xffff] + e00);
            float p1 = __expf(S[t][1] * 0.125f + tbl[ba >> 16] + e01);
            float p2 = __expf(S[t][2] * 0.125f + tbl[bb & 0xffff] + e10);
            float p3 = __expf(S[t][3] * 0.125f + tbl[bb >> 16] + e11);
            lrow0 += p0 + p1;
            lrow1 += p2 + p3;
            __nv_bfloat162 hA, hB, lA, lB;
            hA.x = __float2bfloat16(p0); hA.y = __float2bfloat16(p1);
            hB.x = __float2bfloat16(p2); hB.y = __float2bfloat16(p3);
            lA.x = __float2bfloat16(p0 - __bfloat162float(hA.x));
            lA.y = __float2bfloat16(p1 - __bfloat162float(hA.y));
            lB.x = __float2bfloat16(p2 - __bfloat162float(hB.x));
            lB.y = __float2bfloat16(p3 - __bfloat162float(hB.y));
            ph[t * 2] = *(uint32_t*)&hA; ph[t * 2 + 1] = *(uint32_t*)&hB;
            pl[t * 2] = *(uint32_t*)&lA; pl[t * 2 + 1] = *(uint32_t*)&lB;
        }

        // O += P V  (hh + lh + hl)
#pragma unroll
        for (int c = 0; c < 4; c++) {
            const uint32_t* ah = ph + 4 * c;
            const uint32_t* al = pl + 4 * c;
            uint32_t vrow = vbase +
                            (c * 16 + (((l >> 3) & 1) << 3) + (l & 7)) * 272 +
                            (l >> 4) * 16;
#pragma unroll
            for (int dp = 0; dp < 4; dp++) {
                uint32_t tv[4];
                ldsm4t(tv, vrow + dp * 32);
                mma16816(O[2 * dp], ah, tv);
                mma16816(O[2 * dp + 1], ah, tv + 2);
                mma16816(O[2 * dp], al, tv);
                mma16816(O[2 * dp + 1], al, tv + 2);
                uint32_t tw[4];
                ldsm4t(tw, vrow + 128 + dp * 32);
                mma16816(O[2 * dp], ah, tw);
                mma16816(O[2 * dp + 1], ah, tw + 2);
            }
        }

        if (jt < 15) asm volatile("cp.async.wait_group 0;" ::: "memory");
        __syncthreads();
    }

    // finalize
    lrow0 += __shfl_xor_sync(0xffffffff, lrow0, 1);
    lrow0 += __shfl_xor_sync(0xffffffff, lrow0, 2);
    lrow1 += __shfl_xor_sync(0xffffffff, lrow1, 1);
    lrow1 += __shfl_xor_sync(0xffffffff, lrow1, 2);
    float inv0 = 1.0f / lrow0, inv1 = 1.0f / lrow1;
#pragma unroll
    for (int dt = 0; dt < 8; dt++) {
        int col = h * 64 + dt * 8 + 2 * lr;
        float o0 = O[dt][0] * inv0, o1 = O[dt][1] * inv0;
        float o2 = O[dt][2] * inv1, o3 = O[dt][3] * inv1;
        __nv_bfloat16* d0 = g_a2 + (size_t)(b * N_ + r0g) * 1536 + col;
        __nv_bfloat16* d1 = g_a2 + (size_t)(b * N_ + r0g + 8) * 1536 + col;
        __nv_bfloat162 hv, lv;
        hv.x = __float2bfloat16(o0); hv.y = __float2bfloat16(o1);
        lv.x = __float2bfloat16(o0 - __bfloat162float(hv.x));
        lv.y = __float2bfloat16(o1 - __bfloat162float(hv.y));
        *(uint32_t*)d0 = *(uint32_t*)&hv;
        *(uint32_t*)(d0 + 768) = *(uint32_t*)&lv;
        hv.x = __float2bfloat16(o2); hv.y = __float2bfloat16(o3);
        lv.x = __float2bfloat16(o2 - __bfloat162float(hv.x));
        lv.y = __float2bfloat16(o3 - __bfloat162float(hv.y));
        *(uint32_t*)d1 = *(uint32_t*)&hv;
        *(uint32_t*)(d1 + 768) = *(uint32_t*)&lv;
    }
}

extern "C" void kernel_launch(void* const* d_in, const int* in_sizes, int n_in,
                              void* d_out, int out_size) {
    const float* x = (const float*)d_in[0];
    const float* coords = (const float*)d_in[1];
    const float* elev = (const float*)d_in[2];
    const float* W_qkv = (const float*)d_in[3];
    const float* W_proj = (const float*)d_in[4];
    const float* b_proj = (const float*)d_in[5];
    const float* bias_table = (const float*)d_in[6];
    const float* alpha = (const float*)d_in[7];
    float* out = (float*)d_out;

    cudaFuncSetAttribute(attn3_kernel, cudaFuncAttributeMaxDynamicSharedMemorySize,
                         ATTN_SMEM);
    cudaFuncSetAttribute((const void*)mma_gemm<true, 4>,
                         cudaFuncAttributeMaxDynamicSharedMemorySize,
                         3 * (4 * 32 * 144 + 128 * 144));
    cudaFuncSetAttribute((const void*)mma_gemm<false, 2>,
                         cudaFuncAttributeMaxDynamicSharedMemorySize,
                         3 * (2 * 32 * 144 + 128 * 144));

    prep_all<<<3328 + 2304, 256>>>(x, coords, W_qkv, W_proj);
    mma_gemm<true, 4><<<dim3(ND3_ / 128, 32), 256,
                        3 * (4 * 32 * 144 + 128 * 144)>>>(nullptr, nullptr);
    attn3_kernel<<<dim3(N_ / 128, H_, B_), 256, ATTN_SMEM>>>(elev, bias_table, alpha);
    mma_gemm<false, 2><<<dim3(D_ / 128, 64), 256,
                         3 * (2 * 32 * 144 + 128 * 144)>>>(b_proj, out);
}